// round 1
// baseline (speedup 1.0000x reference)
#include <cuda_runtime.h>

// Equivariant linear: per-irrep block-diagonal matmul.
// Blocks (mul, d, x_off, w_off):
//   (256, 1,   0,     0)
//   (128, 3, 256, 65536)
//   ( 64, 5, 640, 81920)
//   ( 32, 7, 960, 86016)
// y[b, XO + v*d + i] = (1/sqrt(mul)) * sum_u w[WO + v*mul + u] * x[b, XO + u*d + i]

#define FEAT 1184
#define BATCH_N 131072
#define NTHREADS 256

__device__ __forceinline__ unsigned long long pack2(float lo, float hi) {
    unsigned long long r;
    asm("mov.b64 %0, {%1, %2};" : "=l"(r) : "f"(lo), "f"(hi));
    return r;
}
__device__ __forceinline__ void unpack2(unsigned long long v, float &lo, float &hi) {
    asm("mov.b64 {%0, %1}, %2;" : "=f"(lo), "=f"(hi) : "l"(v));
}
// Packed dual-fp32 FMA (sm_100+): d = a*b + d  on two lanes of a 64-bit pair.
__device__ __forceinline__ void fma2(unsigned long long &d, unsigned long long a,
                                     unsigned long long b) {
    asm("fma.rn.f32x2 %0, %1, %2, %0;" : "+l"(d) : "l"(a), "l"(b));
}

// CTA tile: TB batch rows x full (v in [0,MUL), i in [0,D)) outputs.
// M dimension = (b,i) pairs, Mcta = TB*D. K = u, chunked by KU=32.
// Thread tile: TV v-values (as TV/2 packed pairs) x TM m-rows.
template<int MUL, int D, int XO, int WO, int TB, int TV, int TM>
__global__ __launch_bounds__(NTHREADS, 2)
void eqlin_kernel(const float* __restrict__ x, const float* __restrict__ w,
                  float* __restrict__ y)
{
    constexpr int KU   = 32;
    constexpr int NCH  = MUL / KU;           // K chunks
    constexpr int Mcta = TB * D;             // (b,i) rows per CTA
    constexpr int NTV  = MUL / TV;           // threads along v
    constexpr int NTM  = NTHREADS / NTV;     // threads along m
    static_assert(NTM * TM == Mcta, "tile mismatch");
    static_assert((TV % 4) == 0, "TV must be multiple of 4");
    constexpr int XSW  = Mcta + 1;           // odd pad: conflict-free STS scatter
    constexpr int MULW = MUL + 4;            // pad 4: keeps float4 reads aligned
    constexpr int NACC = (TV / 2) * TM;

    __shared__ float xs[KU * XSW];           // xs[u][m],  m = b_local*D + i
    __shared__ float ws[KU * MULW];          // ws[u][v],  pre-scaled by 1/sqrt(MUL)

    const int tid = threadIdx.x;
    const int b0  = blockIdx.x * TB;
    const int tv  = tid % NTV;
    const int tm  = tid / NTV;
    const int v0  = tv * TV;
    const int m0  = tm * TM;

    const float c = rsqrtf((float)MUL);

    unsigned long long acc[NACC];
    #pragma unroll
    for (int a = 0; a < NACC; ++a) acc[a] = 0ull;

    for (int ch = 0; ch < NCH; ++ch) {
        const int u0 = ch * KU;
        __syncthreads();

        // ---- load x chunk: contiguous float4 per row, scatter to u-major smem
        constexpr int NX4 = TB * KU * D / 4 / NTHREADS;
        #pragma unroll
        for (int t = 0; t < NX4; ++t) {
            int f  = (tid + t * NTHREADS) * 4;   // flat float index in chunk
            int bl = f / (KU * D);
            int r  = f % (KU * D);               // (u,i) offset within row slice
            const float4 v4 = *(const float4*)(x + (size_t)(b0 + bl) * FEAT
                                               + XO + u0 * D + r);
            float vv[4] = {v4.x, v4.y, v4.z, v4.w};
            #pragma unroll
            for (int q = 0; q < 4; ++q) {
                int ul = (r + q) / D;
                int il = (r + q) % D;
                xs[ul * XSW + bl * D + il] = vv[q];
            }
        }

        // ---- load w chunk: w[v, u0:u0+KU], store as ws[u][v], scaled
        constexpr int NW4 = MUL * KU / 4 / NTHREADS;
        #pragma unroll
        for (int t = 0; t < NW4; ++t) {
            int f = (tid + t * NTHREADS) * 4;
            int v = f / KU;
            int r = f % KU;
            const float4 v4 = *(const float4*)(w + WO + v * MUL + u0 + r);
            ws[(r + 0) * MULW + v] = v4.x * c;
            ws[(r + 1) * MULW + v] = v4.y * c;
            ws[(r + 2) * MULW + v] = v4.z * c;
            ws[(r + 3) * MULW + v] = v4.w * c;
        }
        __syncthreads();

        // ---- outer-product accumulate with packed f32x2 FMAs
        #pragma unroll 8
        for (int u = 0; u < KU; ++u) {
            unsigned long long xr[TM];
            #pragma unroll
            for (int j = 0; j < TM; ++j) {
                float xv = xs[u * XSW + m0 + j];
                xr[j] = pack2(xv, xv);
            }
            #pragma unroll
            for (int pq = 0; pq < TV / 4; ++pq) {
                const float4 wq = *(const float4*)&ws[u * MULW + v0 + pq * 4];
                unsigned long long w01 = pack2(wq.x, wq.y);
                unsigned long long w23 = pack2(wq.z, wq.w);
                #pragma unroll
                for (int j = 0; j < TM; ++j) {
                    fma2(acc[(pq * 2 + 0) * TM + j], w01, xr[j]);
                    fma2(acc[(pq * 2 + 1) * TM + j], w23, xr[j]);
                }
            }
        }
    }

    // ---- store
    #pragma unroll
    for (int p = 0; p < TV / 2; ++p) {
        #pragma unroll
        for (int j = 0; j < TM; ++j) {
            float lo, hi;
            unpack2(acc[p * TM + j], lo, hi);
            int m = m0 + j;
            int b = b0 + m / D;
            int i = m % D;
            int v = v0 + p * 2;
            y[(size_t)b * FEAT + XO + (size_t)(v + 0) * D + i] = lo;
            y[(size_t)b * FEAT + XO + (size_t)(v + 1) * D + i] = hi;
        }
    }
}

extern "C" void kernel_launch(void* const* d_in, const int* in_sizes, int n_in,
                              void* d_out, int out_size) {
    const float* x = (const float*)d_in[0];
    const float* w = (const float*)d_in[1];
    float* y = (float*)d_out;
    (void)in_sizes; (void)n_in; (void)out_size;

    //                 MUL  D   XO    WO     TB  TV  TM
    eqlin_kernel<256, 1,   0,     0, 64, 16, 4><<<BATCH_N / 64, NTHREADS>>>(x, w, y);
    eqlin_kernel<128, 3, 256, 65536, 32,  8, 6><<<BATCH_N / 32, NTHREADS>>>(x, w, y);
    eqlin_kernel< 64, 5, 640, 81920, 32,  8, 5><<<BATCH_N / 32, NTHREADS>>>(x, w, y);
    eqlin_kernel< 32, 7, 960, 86016, 32,  4, 7><<<BATCH_N / 32, NTHREADS>>>(x, w, y);
}

// round 3
// speedup vs baseline: 1.9460x; 1.9460x over previous
#include <cuda_runtime.h>

// Equivariant linear via block-diagonal GEMMs on tensor cores (3xTF32).
// Blocks (mul, d, x_off, w_off):
//   (256, 1,   0,     0)  (128, 3, 256, 65536)  (64, 5, 640, 81920)  (32, 7, 960, 86016)
// y[b, XO + v*D + i] = (1/sqrt(MUL)) * sum_u w[WO + v*MUL + u] * x[b, XO + u*D + i]
// GEMM view per block: M=MUL (v), K=MUL (u), N=BATCH*D (n = b*D+i).

#define FEAT 1184
#define BATCH_N 131072
#define NT 256

__device__ __forceinline__ float tf32r(float v) {
    float r; asm("cvt.rna.tf32.f32 %0, %1;" : "=f"(r) : "f"(v)); return r;
}

// D += A(16x8,row) * B(8x8,col), tf32 inputs, fp32 accum.
__device__ __forceinline__ void mma8(float* d, const unsigned* a, const unsigned* b) {
    asm volatile("mma.sync.aligned.m16n8k8.row.col.f32.tf32.tf32.f32 "
        "{%0,%1,%2,%3}, {%4,%5,%6,%7}, {%8,%9}, {%0,%1,%2,%3};"
        : "+f"(d[0]), "+f"(d[1]), "+f"(d[2]), "+f"(d[3])
        : "r"(a[0]), "r"(a[1]), "r"(a[2]), "r"(a[3]), "r"(b[0]), "r"(b[1]));
}

template<int MUL, int D, int XO, int WO, int MCTA, int NB, int WM, int WN>
__global__ __launch_bounds__(NT, 2)
void eqlin_mma(const float* __restrict__ x, const float* __restrict__ w,
               float* __restrict__ y)
{
    constexpr int KC   = 16;                 // K chunk (u)
    constexpr int NCH  = MUL / KC;
    constexpr int NCOL = NB * D;             // CTA n-columns
    constexpr int WSS  = KC + 4;             // W smem row stride (conflict-free A frags)
    constexpr int NS   = NCOL + 8;           // X smem row stride (conflict-free B frags)
    constexpr int TMW  = MCTA / WM;          // warp m tile
    constexpr int TNW  = NCOL / WN;          // warp n tile
    constexpr int MF   = TMW / 16;
    constexpr int NF   = TNW / 8;
    static_assert(TMW % 16 == 0 && TNW % 8 == 0, "warp tile");
    static_assert(WM * WN * 32 == NT, "warp grid");
    constexpr int SN    = (MCTA * (NCOL + 2) * 4 <= 49152) ? (NCOL + 2) : NCOL;
    constexpr int LOADB = (MCTA * WSS * 2 + KC * NS * 2) * 4;
    constexpr int EPIB  = MCTA * SN * 4;
    constexpr int SMB   = LOADB > EPIB ? LOADB : EPIB;
    static_assert(SMB <= 49152, "smem");
    static_assert((NB * KC * D) % NT == 0 && (MCTA * KC) % NT == 0, "loader");
    static_assert((NB * MCTA * D) % (4 * NT) == 0, "epilogue");

    __shared__ __align__(16) char smembuf[SMB];
    float* wsh = (float*)smembuf;            // [MCTA][WSS] hi
    float* wsl = wsh + MCTA * WSS;           // lo
    float* xsh = wsl + MCTA * WSS;           // [KC][NS] hi
    float* xsl = xsh + KC * NS;              // lo
    float* S   = (float*)smembuf;            // epilogue [MCTA][SN]

    const int tid = threadIdx.x;
    const int b0  = blockIdx.x * NB;
    const int v0  = blockIdx.y * MCTA;
    const int wid = tid >> 5, lane = tid & 31;
    const int g = lane >> 2, tg = lane & 3;
    const int wm = wid % WM, wn = wid / WM;
    const int mb0 = wm * TMW, nb0 = wn * TNW;
    const float c = rsqrtf((float)MUL);

    float acc[MF][NF][4];
    #pragma unroll
    for (int mf = 0; mf < MF; ++mf)
        #pragma unroll
        for (int nf = 0; nf < NF; ++nf)
            #pragma unroll
            for (int q = 0; q < 4; ++q) acc[mf][nf][q] = 0.f;

    for (int ch = 0; ch < NCH; ++ch) {
        const int u0 = ch * KC;
        __syncthreads();

        // ---- stage X chunk, transposed to [u][n], split hi/lo
        #pragma unroll
        for (int t = 0; t < NB * KC * D / NT; ++t) {
            int f = tid + t * NT;
            int bl = f / (KC * D), r = f % (KC * D);   // r = (u_local, i) flat
            float v = x[(size_t)(b0 + bl) * FEAT + XO + u0 * D + r];
            float h = tf32r(v), l = tf32r(v - h);
            int ul = r / D, il = r % D;
            xsh[ul * NS + bl * D + il] = h;
            xsl[ul * NS + bl * D + il] = l;
        }
        // ---- stage W chunk [m][k], pre-scaled, split hi/lo
        #pragma unroll
        for (int t = 0; t < MCTA * KC / NT; ++t) {
            int f = tid + t * NT;
            int m = f / KC, k = f % KC;
            float v = w[WO + (size_t)(v0 + m) * MUL + u0 + k] * c;
            float h = tf32r(v), l = tf32r(v - h);
            wsh[m * WSS + k] = h;
            wsl[m * WSS + k] = l;
        }
        __syncthreads();

        const unsigned* WH = (const unsigned*)wsh;
        const unsigned* WL = (const unsigned*)wsl;
        const unsigned* XH = (const unsigned*)xsh;
        const unsigned* XL = (const unsigned*)xsl;

        #pragma unroll
        for (int k8 = 0; k8 < KC / 8; ++k8) {
            const int kk = k8 * 8;
            unsigned ah[MF][4], al[MF][4], bh[NF][2], bl2[NF][2];
            #pragma unroll
            for (int mf = 0; mf < MF; ++mf) {
                int mb = mb0 + mf * 16;
                ah[mf][0] = WH[(mb + g) * WSS + kk + tg];
                ah[mf][1] = WH[(mb + g + 8) * WSS + kk + tg];
                ah[mf][2] = WH[(mb + g) * WSS + kk + tg + 4];
                ah[mf][3] = WH[(mb + g + 8) * WSS + kk + tg + 4];
                al[mf][0] = WL[(mb + g) * WSS + kk + tg];
                al[mf][1] = WL[(mb + g + 8) * WSS + kk + tg];
                al[mf][2] = WL[(mb + g) * WSS + kk + tg + 4];
                al[mf][3] = WL[(mb + g + 8) * WSS + kk + tg + 4];
            }
            #pragma unroll
            for (int nf = 0; nf < NF; ++nf) {
                int nn = nb0 + nf * 8 + g;
                bh[nf][0]  = XH[(kk + tg) * NS + nn];
                bh[nf][1]  = XH[(kk + tg + 4) * NS + nn];
                bl2[nf][0] = XL[(kk + tg) * NS + nn];
                bl2[nf][1] = XL[(kk + tg + 4) * NS + nn];
            }
            #pragma unroll
            for (int mf = 0; mf < MF; ++mf)
                #pragma unroll
                for (int nf = 0; nf < NF; ++nf) {
                    mma8(acc[mf][nf], ah[mf], bh[nf]);   // hi*hi
                    mma8(acc[mf][nf], ah[mf], bl2[nf]);  // hi*lo
                    mma8(acc[mf][nf], al[mf], bh[nf]);   // lo*hi
                }
        }
    }

    // ---- epilogue: fragments -> smem [m][n] -> coalesced float4 stores
    __syncthreads();
    #pragma unroll
    for (int mf = 0; mf < MF; ++mf)
        #pragma unroll
        for (int nf = 0; nf < NF; ++nf) {
            int mb = mb0 + mf * 16, nn = nb0 + nf * 8 + 2 * tg;
            S[(mb + g) * SN + nn]     = acc[mf][nf][0];
            S[(mb + g) * SN + nn + 1] = acc[mf][nf][1];
            S[(mb + g + 8) * SN + nn]     = acc[mf][nf][2];
            S[(mb + g + 8) * SN + nn + 1] = acc[mf][nf][3];
        }
    __syncthreads();

    constexpr int ROW = MCTA * D;   // contiguous output span per batch row
    #pragma unroll
    for (int t = 0; t < NB * ROW / 4 / NT; ++t) {
        int f4 = (tid + t * NT) * 4;
        int bl = f4 / ROW, r = f4 % ROW;
        float4 o;
        o.x = S[((r + 0) / D) * SN + bl * D + (r + 0) % D];
        o.y = S[((r + 1) / D) * SN + bl * D + (r + 1) % D];
        o.z = S[((r + 2) / D) * SN + bl * D + (r + 2) % D];
        o.w = S[((r + 3) / D) * SN + bl * D + (r + 3) % D];
        *(float4*)(y + (size_t)(b0 + bl) * FEAT + XO + v0 * D + r) = o;
    }
}

extern "C" void kernel_launch(void* const* d_in, const int* in_sizes, int n_in,
                              void* d_out, int out_size) {
    const float* x = (const float*)d_in[0];
    const float* w = (const float*)d_in[1];
    float* y = (float*)d_out;
    (void)in_sizes; (void)n_in; (void)out_size;

    //        MUL  D   XO    WO   MCTA NB WM WN
    eqlin_mma<256, 1,   0,     0, 128, 64, 4, 2><<<dim3(BATCH_N / 64, 2), NT>>>(x, w, y);
    eqlin_mma<128, 3, 256, 65536, 128, 32, 4, 2><<<dim3(BATCH_N / 32, 1), NT>>>(x, w, y);
    eqlin_mma< 64, 5, 640, 81920,  64, 32, 2, 4><<<dim3(BATCH_N / 32, 1), NT>>>(x, w, y);
    eqlin_mma< 32, 7, 960, 86016,  32, 32, 2, 4><<<dim3(BATCH_N / 32, 1), NT>>>(x, w, y);
}